// round 15
// baseline (speedup 1.0000x reference)
#include <cuda_runtime.h>
#include <cuda_bf16.h>
#include <math.h>
#include <stdint.h>

#define BATCH   2
#define SEQ     2048
#define DMODEL  1024
#define NHEAD   16
#define HDIM    64
#define BT      (BATCH * SEQ)          // 4096
#define N_QKV   (3 * DMODEL)           // 3072

// split-bf16 tensors
__device__ __nv_bfloat16 g_Qh[BATCH * NHEAD * SEQ * HDIM];  // [b,h,t,d], pre-scaled 1/8
__device__ __nv_bfloat16 g_Ql[BATCH * NHEAD * SEQ * HDIM];
__device__ __nv_bfloat16 g_Kh[BATCH * NHEAD * SEQ * HDIM];  // [b,h,t,d]
__device__ __nv_bfloat16 g_Kl[BATCH * NHEAD * SEQ * HDIM];
__device__ __nv_bfloat16 g_Vth[BATCH * NHEAD * HDIM * SEQ]; // [b,h,d,t]
__device__ __nv_bfloat16 g_Vtl[BATCH * NHEAD * HDIM * SEQ];
__device__ __nv_bfloat16 g_xh[BT * DMODEL];
__device__ __nv_bfloat16 g_xl[BT * DMODEL];
__device__ __nv_bfloat16 g_yh[BT * DMODEL];
__device__ __nv_bfloat16 g_yl[BT * DMODEL];
__device__ __nv_bfloat16 g_wqh[N_QKV * DMODEL];     // transposed [n][k]
__device__ __nv_bfloat16 g_wql[N_QKV * DMODEL];
__device__ __nv_bfloat16 g_woh[DMODEL * DMODEL];    // transposed [n][k]
__device__ __nv_bfloat16 g_wol[DMODEL * DMODEL];
__device__ float g_cos[SEQ * HDIM];
__device__ float g_sin[SEQ * HDIM];

// ---------------------------------------------------------------------------
__device__ __forceinline__ void split2(float v, __nv_bfloat16& h, __nv_bfloat16& l) {
    h = __float2bfloat16(v);
    l = __float2bfloat16(v - __bfloat162float(h));
}
__device__ __forceinline__ uint32_t pack2(__nv_bfloat16 a, __nv_bfloat16 b) {
    uint16_t ua = *reinterpret_cast<uint16_t*>(&a);
    uint16_t ub = *reinterpret_cast<uint16_t*>(&b);
    return (uint32_t)ua | ((uint32_t)ub << 16);
}

// ===========================================================================
// Fused prep: rope table | x split | w_qkv transpose-split | w_out t-split.
// ===========================================================================
#define ROPE_BLKS   ((SEQ * HDIM) / 256)                 // 512
#define SPLITX_BLKS ((BT * DMODEL) / 4 / 256)            // 4096
#define WQ_NB       (N_QKV / 32)                         // 96
#define WQ_BLKS     (WQ_NB * (DMODEL / 32))              // 3072
#define WO_NB       (DMODEL / 32)                        // 32
#define WO_BLKS     (WO_NB * (DMODEL / 32))              // 1024
#define PREP_BLKS   (ROPE_BLKS + SPLITX_BLKS + WQ_BLKS + WO_BLKS)

__global__ __launch_bounds__(256)
void prep_kernel(const float* __restrict__ x,
                 const float* __restrict__ w_qkv,
                 const float* __restrict__ w_out)
{
    __shared__ float tile[32][33];
    const int b   = blockIdx.x;
    const int tid = threadIdx.x;

    if (b < ROPE_BLKS) {
        int i = b * 256 + tid;
        int t = i >> 6;
        int d = i & 63;
        int fi = (d < 32) ? d : d - 32;
        float inv = powf(10000.0f, -((float)fi) / 32.0f);
        float ang = (float)t * inv;
        g_cos[i] = cosf(ang);
        g_sin[i] = sinf(ang);
        return;
    }
    if (b < ROPE_BLKS + SPLITX_BLKS) {
        int i = ((b - ROPE_BLKS) * 256 + tid) * 4;
        float4 v = *reinterpret_cast<const float4*>(x + i);
        __nv_bfloat16 h[4], l[4];
        split2(v.x, h[0], l[0]); split2(v.y, h[1], l[1]);
        split2(v.z, h[2], l[2]); split2(v.w, h[3], l[3]);
        *reinterpret_cast<uint2*>(g_xh + i) = *reinterpret_cast<uint2*>(h);
        *reinterpret_cast<uint2*>(g_xl + i) = *reinterpret_cast<uint2*>(l);
        return;
    }

    const float* W;
    __nv_bfloat16 *th, *tl;
    int n0, k0, N;
    if (b < ROPE_BLKS + SPLITX_BLKS + WQ_BLKS) {
        int bb = b - (ROPE_BLKS + SPLITX_BLKS);
        W = w_qkv; th = g_wqh; tl = g_wql; N = N_QKV;
        n0 = (bb % WQ_NB) * 32;
        k0 = (bb / WQ_NB) * 32;
    } else {
        int bb = b - (ROPE_BLKS + SPLITX_BLKS + WQ_BLKS);
        W = w_out; th = g_woh; tl = g_wol; N = DMODEL;
        n0 = (bb % WO_NB) * 32;
        k0 = (bb / WO_NB) * 32;
    }
    const int tx = tid & 31, ty = tid >> 5;
    #pragma unroll
    for (int j = 0; j < 4; j++)
        tile[ty + j * 8][tx] = W[(size_t)(k0 + ty + j * 8) * N + n0 + tx];
    __syncthreads();
    #pragma unroll
    for (int j = 0; j < 4; j++) {
        float v = tile[tx][ty + j * 8];
        __nv_bfloat16 h, l;
        split2(v, h, l);
        size_t o = (size_t)(n0 + ty + j * 8) * DMODEL + k0 + tx;
        th[o] = h;
        tl[o] = l;
    }
}

// ===========================================================================
#define CP16(dst, src) \
    asm volatile("cp.async.cg.shared.global [%0], [%1], 16;" \
                 :: "r"(dst), "l"(src))
#define CP_COMMIT() asm volatile("cp.async.commit_group;")
#define CP_WAIT1()  asm volatile("cp.async.wait_group 1;")
#define CP_WAIT0()  asm volatile("cp.async.wait_group 0;")

__device__ __forceinline__ void mma16816(float* c, const uint32_t* a, const uint32_t* b) {
    asm volatile(
        "mma.sync.aligned.m16n8k16.row.col.f32.bf16.bf16.f32 "
        "{%0,%1,%2,%3}, {%4,%5,%6,%7}, {%8,%9}, {%0,%1,%2,%3};"
        : "+f"(c[0]), "+f"(c[1]), "+f"(c[2]), "+f"(c[3])
        : "r"(a[0]), "r"(a[1]), "r"(a[2]), "r"(a[3]), "r"(b[0]), "r"(b[1]));
}

// ===========================================================================
// mma.sync split-bf16 GEMM.  CTA 128x256, K-chunk 32, 8 warps (warp 64x64).
// 2-stage cp.async.  D += Ah*Bh + Ah*Bl + Al*Bh, issued TERM-MAJOR so
// consecutive MMAs hit different accumulators (32-instr dependency distance).
// ===========================================================================
#define ROWB    80
#define AARRB   (128 * ROWB)            // 10240
#define BARRB   (256 * ROWB)            // 20480
#define STAGEB  (2 * AARRB + 2 * BARRB) // 61440: [Ah][Al][Bh][Bl]
#define OFF_AL  (AARRB)
#define OFF_BH  (2 * AARRB)
#define OFF_BL  (2 * AARRB + BARRB)
#define GEMM_SMEM (2 * STAGEB)          // 122880

template <int EPI>
__global__ __launch_bounds__(256, 1)
void mma_gemm_kernel(const __nv_bfloat16* __restrict__ Ah_g,
                     const __nv_bfloat16* __restrict__ Al_g,
                     const __nv_bfloat16* __restrict__ Bh_g,
                     const __nv_bfloat16* __restrict__ Bl_g,
                     float* __restrict__ C, int M, int N, int K)
{
    extern __shared__ char smc[];
    const uint32_t smem_u32 = (uint32_t)__cvta_generic_to_shared(smc);

    const int tid  = threadIdx.x;
    const int lane = tid & 31;
    const int wid  = tid >> 5;
    const int wm   = wid & 1;
    const int wn   = wid >> 1;
    const int g    = lane >> 2;
    const int t    = lane & 3;
    const int m0   = blockIdx.y * 128;
    const int n0   = blockIdx.x * 256;

    const int ld_row = tid >> 2;
    const int ld_seg = tid & 3;

    float acc[4][8][4];
    #pragma unroll
    for (int a = 0; a < 4; a++)
        #pragma unroll
        for (int b = 0; b < 8; b++)
            #pragma unroll
            for (int c = 0; c < 4; c++) acc[a][b][c] = 0.0f;

    #define LOAD_STAGE(kt, s) do {                                            \
        uint32_t sb = smem_u32 + (s) * STAGEB;                                \
        _Pragma("unroll")                                                     \
        for (int i = 0; i < 2; i++) {                                         \
            int row = ld_row + i * 64;                                        \
            uint32_t so = sb + row * ROWB + ld_seg * 16;                      \
            size_t  ga = (size_t)(m0 + row) * K + (kt) * 32 + ld_seg * 8;     \
            CP16(so,          Ah_g + ga);                                     \
            CP16(so + OFF_AL, Al_g + ga);                                     \
        }                                                                     \
        _Pragma("unroll")                                                     \
        for (int i = 0; i < 4; i++) {                                         \
            int row = ld_row + i * 64;                                        \
            uint32_t so = sb + row * ROWB + ld_seg * 16;                      \
            size_t  gb = (size_t)(n0 + row) * K + (kt) * 32 + ld_seg * 8;     \
            CP16(so + OFF_BH, Bh_g + gb);                                     \
            CP16(so + OFF_BL, Bl_g + gb);                                     \
        }                                                                     \
    } while (0)

    const int nk = K >> 5;
    LOAD_STAGE(0, 0);
    CP_COMMIT();

    for (int kt = 0; kt < nk; kt++) {
        const int s = kt & 1;
        if (kt + 1 < nk) {
            LOAD_STAGE(kt + 1, s ^ 1);
            CP_COMMIT();
            CP_WAIT1();
        } else {
            CP_WAIT0();
        }
        __syncthreads();

        const char* st  = smc + s * STAGEB;
        const char* pAh = st;
        const char* pAl = st + OFF_AL;
        const char* pBh = st + OFF_BH;
        const char* pBl = st + OFF_BL;

        #pragma unroll
        for (int ks = 0; ks < 2; ks++) {
            const int kb = ks * 32;
            uint32_t af_h[4][4], af_l[4][4], bf_h[8][2], bf_l[8][2];
            #pragma unroll
            for (int mt = 0; mt < 4; mt++) {
                int off = (wm * 64 + mt * 16 + g) * ROWB + kb + t * 4;
                af_h[mt][0] = *(const uint32_t*)(pAh + off);
                af_h[mt][1] = *(const uint32_t*)(pAh + off + 8 * ROWB);
                af_h[mt][2] = *(const uint32_t*)(pAh + off + 16);
                af_h[mt][3] = *(const uint32_t*)(pAh + off + 8 * ROWB + 16);
                af_l[mt][0] = *(const uint32_t*)(pAl + off);
                af_l[mt][1] = *(const uint32_t*)(pAl + off + 8 * ROWB);
                af_l[mt][2] = *(const uint32_t*)(pAl + off + 16);
                af_l[mt][3] = *(const uint32_t*)(pAl + off + 8 * ROWB + 16);
            }
            #pragma unroll
            for (int nt = 0; nt < 8; nt++) {
                int off = (wn * 64 + nt * 8 + g) * ROWB + kb + t * 4;
                bf_h[nt][0] = *(const uint32_t*)(pBh + off);
                bf_h[nt][1] = *(const uint32_t*)(pBh + off + 16);
                bf_l[nt][0] = *(const uint32_t*)(pBl + off);
                bf_l[nt][1] = *(const uint32_t*)(pBl + off + 16);
            }
            // term-major: 3 passes of 32 independent MMAs
            #pragma unroll
            for (int mt = 0; mt < 4; mt++)
                #pragma unroll
                for (int nt = 0; nt < 8; nt++)
                    mma16816(acc[mt][nt], af_h[mt], bf_h[nt]);
            #pragma unroll
            for (int mt = 0; mt < 4; mt++)
                #pragma unroll
                for (int nt = 0; nt < 8; nt++)
                    mma16816(acc[mt][nt], af_h[mt], bf_l[nt]);
            #pragma unroll
            for (int mt = 0; mt < 4; mt++)
                #pragma unroll
                for (int nt = 0; nt < 8; nt++)
                    mma16816(acc[mt][nt], af_l[mt], bf_h[nt]);
        }
        __syncthreads();
    }
    #undef LOAD_STAGE

    #pragma unroll
    for (int mt = 0; mt < 4; mt++) {
        const int mr0 = m0 + wm * 64 + mt * 16 + g;
        #pragma unroll
        for (int nt = 0; nt < 8; nt++) {
            const int col = n0 + wn * 64 + nt * 8 + 2 * t;
            const float* a = acc[mt][nt];
            if (EPI == 2) {
                *reinterpret_cast<float2*>(C + (size_t)mr0 * N + col) =
                    make_float2(a[0], a[1]);
                *reinterpret_cast<float2*>(C + (size_t)(mr0 + 8) * N + col) =
                    make_float2(a[2], a[3]);
            } else {
                const int section = col >> 10;
                const int within  = col & 1023;
                const int h       = within >> 6;
                const int d       = within & 63;      // even
                #pragma unroll
                for (int rr = 0; rr < 2; rr++) {
                    const int m  = mr0 + rr * 8;
                    const int bb = m >> 11;
                    const int tt = m & 2047;
                    float e = a[rr * 2 + 0], o = a[rr * 2 + 1];
                    if (section == 2) {
                        size_t vb = ((size_t)(bb * NHEAD + h) * HDIM + d) * SEQ + tt;
                        __nv_bfloat16 h0, l0, h1, l1;
                        split2(e, h0, l0);
                        split2(o, h1, l1);
                        g_Vth[vb]       = h0;
                        g_Vtl[vb]       = l0;
                        g_Vth[vb + SEQ] = h1;
                        g_Vtl[vb + SEQ] = l1;
                    } else {
                        int idx = tt * HDIM + d;
                        float c0 = g_cos[idx],     s0 = g_sin[idx];
                        float c1 = g_cos[idx + 1], s1 = g_sin[idx + 1];
                        float r0 = e * c0 - o * s0;
                        float r1 = o * c1 + e * s1;
                        size_t base = ((size_t)(bb * NHEAD + h) * SEQ + tt) * HDIM + d;
                        __nv_bfloat16 h0, l0, h1, l1;
                        if (section == 0) {
                            r0 *= 0.125f; r1 *= 0.125f;
                            split2(r0, h0, l0); split2(r1, h1, l1);
                            *reinterpret_cast<uint32_t*>(g_Qh + base) = pack2(h0, h1);
                            *reinterpret_cast<uint32_t*>(g_Ql + base) = pack2(l0, l1);
                        } else {
                            split2(r0, h0, l0); split2(r1, h1, l1);
                            *reinterpret_cast<uint32_t*>(g_Kh + base) = pack2(h0, h1);
                            *reinterpret_cast<uint32_t*>(g_Kl + base) = pack2(l0, l1);
                        }
                    }
                }
            }
        }
    }
}

// ===========================================================================
// Tensor-core flash attention, term-major MMA issue.
// S = QhKh + QhKl + QlKh; P split in regs; O += PhVh + PhVl + PlVh.
// ===========================================================================
#define KROW    144
#define VROW    272
#define KTILE_B (128 * KROW)
#define VTILE_B (64 * VROW)
#define ATT_STAGE (2 * KTILE_B + 2 * VTILE_B)   // 71680
#define ATT_SMEM  (2 * ATT_STAGE)               // 143360

__global__ __launch_bounds__(256, 1)
void attn_mma_kernel()
{
    extern __shared__ char smc[];
    const uint32_t smem_u32 = (uint32_t)__cvta_generic_to_shared(smc);

    const int tid  = threadIdx.x;
    const int lane = tid & 31;
    const int w    = tid >> 5;
    const int g    = lane >> 2;
    const int t    = lane & 3;
    const int qt   = blockIdx.x;
    const int hh   = blockIdx.y;
    const int bb   = blockIdx.z;

    const size_t head_base = (size_t)(bb * NHEAD + hh) * SEQ * HDIM;
    const size_t vt_base   = (size_t)(bb * NHEAD + hh) * HDIM * SEQ;

    uint32_t qh[4][4], ql[4][4];
    {
        const int r0 = qt * 128 + w * 16 + g;
        const char* pqh = (const char*)(g_Qh + head_base);
        const char* pql = (const char*)(g_Ql + head_base);
        #pragma unroll
        for (int ks = 0; ks < 4; ks++) {
            int o00 = r0 * 128 + ks * 32 + t * 4;
            int o10 = o00 + 8 * 128;
            qh[ks][0] = *(const uint32_t*)(pqh + o00);
            qh[ks][1] = *(const uint32_t*)(pqh + o10);
            qh[ks][2] = *(const uint32_t*)(pqh + o00 + 16);
            qh[ks][3] = *(const uint32_t*)(pqh + o10 + 16);
            ql[ks][0] = *(const uint32_t*)(pql + o00);
            ql[ks][1] = *(const uint32_t*)(pql + o10);
            ql[ks][2] = *(const uint32_t*)(pql + o00 + 16);
            ql[ks][3] = *(const uint32_t*)(pql + o10 + 16);
        }
    }

    float m_[2] = {-INFINITY, -INFINITY};
    float l_[2] = {0.0f, 0.0f};
    float o[8][4];
    #pragma unroll
    for (int nt = 0; nt < 8; nt++)
        #pragma unroll
        for (int c = 0; c < 4; c++) o[nt][c] = 0.0f;

    #define LOAD_KV(kt, s) do {                                               \
        uint32_t sb = smem_u32 + (s) * ATT_STAGE;                             \
        _Pragma("unroll")                                                     \
        for (int i = 0; i < 4; i++) {                                         \
            int c    = tid + i * 256;                                         \
            int krow = c >> 3, kcc = c & 7;                                   \
            size_t kg = head_base + (size_t)((kt) * 128 + krow) * 64 + kcc * 8; \
            uint32_t kd = sb + krow * KROW + kcc * 16;                        \
            CP16(kd,            g_Kh + kg);                                   \
            CP16(kd + KTILE_B,  g_Kl + kg);                                   \
            int vrow = c >> 4, vcc = c & 15;                                  \
            size_t vg = vt_base + (size_t)vrow * SEQ + (kt) * 128 + vcc * 8;  \
            uint32_t vd = sb + 2 * KTILE_B + vrow * VROW + vcc * 16;          \
            CP16(vd,            g_Vth + vg);                                  \
            CP16(vd + VTILE_B,  g_Vtl + vg);                                  \
        }                                                                     \
    } while (0)

    LOAD_KV(0, 0);
    CP_COMMIT();

    const int nkt = SEQ / 128;
    for (int kt = 0; kt < nkt; kt++) {
        const int s = kt & 1;
        if (kt + 1 < nkt) {
            LOAD_KV(kt + 1, s ^ 1);
            CP_COMMIT();
            CP_WAIT1();
        } else {
            CP_WAIT0();
        }
        __syncthreads();

        const char* st   = smc + s * ATT_STAGE;
        const char* pKh  = st;
        const char* pKl  = st + KTILE_B;
        const char* pVh  = st + 2 * KTILE_B;
        const char* pVl  = st + 2 * KTILE_B + VTILE_B;

        // ---- S = Q K^T : term-major in groups of 8 n-tiles ----
        float sacc[16][4];
        #pragma unroll
        for (int nt = 0; nt < 16; nt++)
            #pragma unroll
            for (int c = 0; c < 4; c++) sacc[nt][c] = 0.0f;

        #pragma unroll
        for (int ks = 0; ks < 4; ks++) {
            #pragma unroll
            for (int grp = 0; grp < 2; grp++) {
                uint32_t bh8[8][2], bl8[8][2];
                #pragma unroll
                for (int j = 0; j < 8; j++) {
                    const int nt = grp * 8 + j;
                    const int rowb = (nt * 8 + g) * KROW + ks * 32 + t * 4;
                    bh8[j][0] = *(const uint32_t*)(pKh + rowb);
                    bh8[j][1] = *(const uint32_t*)(pKh + rowb + 16);
                    bl8[j][0] = *(const uint32_t*)(pKl + rowb);
                    bl8[j][1] = *(const uint32_t*)(pKl + rowb + 16);
                }
                #pragma unroll
                for (int j = 0; j < 8; j++)
                    mma16816(sacc[grp * 8 + j], qh[ks], bh8[j]);
                #pragma unroll
                for (int j = 0; j < 8; j++)
                    mma16816(sacc[grp * 8 + j], qh[ks], bl8[j]);
                #pragma unroll
                for (int j = 0; j < 8; j++)
                    mma16816(sacc[grp * 8 + j], ql[ks], bh8[j]);
            }
        }

        // ---- online softmax ----
        float alpha[2];
        #pragma unroll
        for (int rr = 0; rr < 2; rr++) {
            float mx = -INFINITY;
            #pragma unroll
            for (int nt = 0; nt < 16; nt++)
                mx = fmaxf(mx, fmaxf(sacc[nt][rr * 2], sacc[nt][rr * 2 + 1]));
            mx = fmaxf(mx, __shfl_xor_sync(0xffffffffu, mx, 1));
            mx = fmaxf(mx, __shfl_xor_sync(0xffffffffu, mx, 2));
            float mnew = fmaxf(m_[rr], mx);
            alpha[rr] = __expf(m_[rr] - mnew);
            float sum = 0.0f;
            #pragma unroll
            for (int nt = 0; nt < 16; nt++) {
                float p0 = __expf(sacc[nt][rr * 2]     - mnew);
                float p1 = __expf(sacc[nt][rr * 2 + 1] - mnew);
                sacc[nt][rr * 2]     = p0;
                sacc[nt][rr * 2 + 1] = p1;
                sum += p0 + p1;
            }
            sum += __shfl_xor_sync(0xffffffffu, sum, 1);
            sum += __shfl_xor_sync(0xffffffffu, sum, 2);
            l_[rr] = l_[rr] * alpha[rr] + sum;
            m_[rr] = mnew;
        }
        #pragma unroll
        for (int nt = 0; nt < 8; nt++) {
            o[nt][0] *= alpha[0]; o[nt][1] *= alpha[0];
            o[nt][2] *= alpha[1]; o[nt][3] *= alpha[1];
        }

        // ---- P -> split bf16 A-fragments ----
        uint32_t aph[8][4], apl[8][4];
        #pragma unroll
        for (int j = 0; j < 8; j++) {
            #pragma unroll
            for (int half = 0; half < 2; half++) {
                const float* sv = sacc[2 * j + half];
                __nv_bfloat16 h0, l0, h1, l1;
                split2(sv[0], h0, l0); split2(sv[1], h1, l1);
                aph[j][half * 2 + 0] = pack2(h0, h1);
                apl[j][half * 2 + 0] = pack2(l0, l1);
                split2(sv[2], h0, l0); split2(sv[3], h1, l1);
                aph[j][half * 2 + 1] = pack2(h0, h1);
                apl[j][half * 2 + 1] = pack2(l0, l1);
            }
        }

        // ---- O += P V : term-major per k-tile j (8 independent o[nt]) ----
        #pragma unroll
        for (int j = 0; j < 8; j++) {
            uint32_t vh8[8][2], vl8[8][2];
            #pragma unroll
            for (int nt = 0; nt < 8; nt++) {
                const int rowb = (nt * 8 + g) * VROW + j * 32 + t * 4;
                vh8[nt][0] = *(const uint32_t*)(pVh + rowb);
                vh8[nt][1] = *(const uint32_t*)(pVh + rowb + 16);
                vl8[nt][0] = *(const uint32_t*)(pVl + rowb);
                vl8[nt][1] = *(const uint32_t*)(pVl + rowb + 16);
            }
            #pragma unroll
            for (int nt = 0; nt < 8; nt++)
                mma16816(o[nt], aph[j], vh8[nt]);
            #pragma unroll
            for (int nt = 0; nt < 8; nt++)
                mma16816(o[nt], aph[j], vl8[nt]);
            #pragma unroll
            for (int nt = 0; nt < 8; nt++)
                mma16816(o[nt], apl[j], vh8[nt]);
        }
        __syncthreads();
    }

    const float inv0 = 1.0f / l_[0];
    const float inv1 = 1.0f / l_[1];
    #pragma unroll
    for (int rr = 0; rr < 2; rr++) {
        const int row = qt * 128 + w * 16 + g + rr * 8;
        const float inv = rr ? inv1 : inv0;
        size_t base = ((size_t)bb * SEQ + row) * DMODEL + hh * HDIM;
        #pragma unroll
        for (int nt = 0; nt < 8; nt++) {
            const int d = nt * 8 + 2 * t;
            float y0 = o[nt][rr * 2]     * inv;
            float y1 = o[nt][rr * 2 + 1] * inv;
            __nv_bfloat16 h0, l0, h1, l1;
            split2(y0, h0, l0); split2(y1, h1, l1);
            *reinterpret_cast<uint32_t*>(g_yh + base + d) = pack2(h0, h1);
            *reinterpret_cast<uint32_t*>(g_yl + base + d) = pack2(l0, l1);
        }
    }
}

// ---------------------------------------------------------------------------
extern "C" void kernel_launch(void* const* d_in, const int* in_sizes, int n_in,
                              void* d_out, int out_size)
{
    const float* x     = (const float*)d_in[0];
    const float* w_qkv = (const float*)d_in[1];
    const float* w_out = (const float*)d_in[2];
    float* out = (float*)d_out;

    static bool attr_done = false;
    if (!attr_done) {
        cudaFuncSetAttribute(mma_gemm_kernel<1>,
                             cudaFuncAttributeMaxDynamicSharedMemorySize, GEMM_SMEM);
        cudaFuncSetAttribute(mma_gemm_kernel<2>,
                             cudaFuncAttributeMaxDynamicSharedMemorySize, GEMM_SMEM);
        cudaFuncSetAttribute(attn_mma_kernel,
                             cudaFuncAttributeMaxDynamicSharedMemorySize, ATT_SMEM);
        attr_done = true;
    }

    __nv_bfloat16 *xh, *xl, *yh, *yl, *wqh, *wql, *woh, *wol;
    cudaGetSymbolAddress((void**)&xh,  g_xh);
    cudaGetSymbolAddress((void**)&xl,  g_xl);
    cudaGetSymbolAddress((void**)&yh,  g_yh);
    cudaGetSymbolAddress((void**)&yl,  g_yl);
    cudaGetSymbolAddress((void**)&wqh, g_wqh);
    cudaGetSymbolAddress((void**)&wql, g_wql);
    cudaGetSymbolAddress((void**)&woh, g_woh);
    cudaGetSymbolAddress((void**)&wol, g_wol);

    prep_kernel<<<PREP_BLKS, 256>>>(x, w_qkv, w_out);

    mma_gemm_kernel<1><<<dim3(N_QKV / 256, BT / 128), 256, GEMM_SMEM>>>(
        xh, xl, wqh, wql, nullptr, BT, N_QKV, DMODEL);

    attn_mma_kernel<<<dim3(SEQ / 128, NHEAD, BATCH), 256, ATT_SMEM>>>();

    mma_gemm_kernel<2><<<dim3(DMODEL / 256, BT / 128), 256, GEMM_SMEM>>>(
        yh, yl, woh, wol, out, BT, DMODEL, DMODEL);
}

// round 17
// speedup vs baseline: 1.0201x; 1.0201x over previous
#include <cuda_runtime.h>
#include <cuda_bf16.h>
#include <math.h>
#include <stdint.h>

#define BATCH   2
#define SEQ     2048
#define DMODEL  1024
#define NHEAD   16
#define HDIM    64
#define BT      (BATCH * SEQ)          // 4096
#define N_QKV   (3 * DMODEL)           // 3072

// split-bf16 tensors
__device__ __nv_bfloat16 g_Qh[BATCH * NHEAD * SEQ * HDIM];  // [b,h,t,d], pre-scaled 1/8
__device__ __nv_bfloat16 g_Ql[BATCH * NHEAD * SEQ * HDIM];
__device__ __nv_bfloat16 g_Kh[BATCH * NHEAD * SEQ * HDIM];  // [b,h,t,d]
__device__ __nv_bfloat16 g_Kl[BATCH * NHEAD * SEQ * HDIM];
__device__ __nv_bfloat16 g_Vth[BATCH * NHEAD * HDIM * SEQ]; // [b,h,d,t]
__device__ __nv_bfloat16 g_Vtl[BATCH * NHEAD * HDIM * SEQ];
__device__ __nv_bfloat16 g_xh[BT * DMODEL];
__device__ __nv_bfloat16 g_xl[BT * DMODEL];
__device__ __nv_bfloat16 g_yh[BT * DMODEL];
__device__ __nv_bfloat16 g_yl[BT * DMODEL];
__device__ __nv_bfloat16 g_wqh[N_QKV * DMODEL];     // transposed [n][k]
__device__ __nv_bfloat16 g_wql[N_QKV * DMODEL];
__device__ __nv_bfloat16 g_woh[DMODEL * DMODEL];    // transposed [n][k]
__device__ __nv_bfloat16 g_wol[DMODEL * DMODEL];
__device__ float g_cos[SEQ * HDIM];
__device__ float g_sin[SEQ * HDIM];

// ---------------------------------------------------------------------------
__device__ __forceinline__ void split2(float v, __nv_bfloat16& h, __nv_bfloat16& l) {
    h = __float2bfloat16(v);
    l = __float2bfloat16(v - __bfloat162float(h));
}
__device__ __forceinline__ uint32_t pack2(__nv_bfloat16 a, __nv_bfloat16 b) {
    uint16_t ua = *reinterpret_cast<uint16_t*>(&a);
    uint16_t ub = *reinterpret_cast<uint16_t*>(&b);
    return (uint32_t)ua | ((uint32_t)ub << 16);
}

// ===========================================================================
// Fused prep: rope table | x split | w_qkv transpose-split | w_out t-split.
// ===========================================================================
#define ROPE_BLKS   ((SEQ * HDIM) / 256)                 // 512
#define SPLITX_BLKS ((BT * DMODEL) / 4 / 256)            // 4096
#define WQ_NB       (N_QKV / 32)                         // 96
#define WQ_BLKS     (WQ_NB * (DMODEL / 32))              // 3072
#define WO_NB       (DMODEL / 32)                        // 32
#define WO_BLKS     (WO_NB * (DMODEL / 32))              // 1024
#define PREP_BLKS   (ROPE_BLKS + SPLITX_BLKS + WQ_BLKS + WO_BLKS)

__global__ __launch_bounds__(256)
void prep_kernel(const float* __restrict__ x,
                 const float* __restrict__ w_qkv,
                 const float* __restrict__ w_out)
{
    __shared__ float tile[32][33];
    const int b   = blockIdx.x;
    const int tid = threadIdx.x;

    if (b < ROPE_BLKS) {
        int i = b * 256 + tid;
        int t = i >> 6;
        int d = i & 63;
        int fi = (d < 32) ? d : d - 32;
        float inv = powf(10000.0f, -((float)fi) / 32.0f);
        float ang = (float)t * inv;
        g_cos[i] = cosf(ang);
        g_sin[i] = sinf(ang);
        return;
    }
    if (b < ROPE_BLKS + SPLITX_BLKS) {
        int i = ((b - ROPE_BLKS) * 256 + tid) * 4;
        float4 v = *reinterpret_cast<const float4*>(x + i);
        __nv_bfloat16 h[4], l[4];
        split2(v.x, h[0], l[0]); split2(v.y, h[1], l[1]);
        split2(v.z, h[2], l[2]); split2(v.w, h[3], l[3]);
        *reinterpret_cast<uint2*>(g_xh + i) = *reinterpret_cast<uint2*>(h);
        *reinterpret_cast<uint2*>(g_xl + i) = *reinterpret_cast<uint2*>(l);
        return;
    }

    const float* W;
    __nv_bfloat16 *th, *tl;
    int n0, k0, N;
    if (b < ROPE_BLKS + SPLITX_BLKS + WQ_BLKS) {
        int bb = b - (ROPE_BLKS + SPLITX_BLKS);
        W = w_qkv; th = g_wqh; tl = g_wql; N = N_QKV;
        n0 = (bb % WQ_NB) * 32;
        k0 = (bb / WQ_NB) * 32;
    } else {
        int bb = b - (ROPE_BLKS + SPLITX_BLKS + WQ_BLKS);
        W = w_out; th = g_woh; tl = g_wol; N = DMODEL;
        n0 = (bb % WO_NB) * 32;
        k0 = (bb / WO_NB) * 32;
    }
    const int tx = tid & 31, ty = tid >> 5;
    #pragma unroll
    for (int j = 0; j < 4; j++)
        tile[ty + j * 8][tx] = W[(size_t)(k0 + ty + j * 8) * N + n0 + tx];
    __syncthreads();
    #pragma unroll
    for (int j = 0; j < 4; j++) {
        float v = tile[tx][ty + j * 8];
        __nv_bfloat16 h, l;
        split2(v, h, l);
        size_t o = (size_t)(n0 + ty + j * 8) * DMODEL + k0 + tx;
        th[o] = h;
        tl[o] = l;
    }
}

// ===========================================================================
#define CP16(dst, src) \
    asm volatile("cp.async.cg.shared.global [%0], [%1], 16;" \
                 :: "r"(dst), "l"(src))
#define CP_COMMIT() asm volatile("cp.async.commit_group;")
#define CP_WAIT1()  asm volatile("cp.async.wait_group 1;")
#define CP_WAIT0()  asm volatile("cp.async.wait_group 0;")

__device__ __forceinline__ void mma16816(float* c, const uint32_t* a, const uint32_t* b) {
    asm volatile(
        "mma.sync.aligned.m16n8k16.row.col.f32.bf16.bf16.f32 "
        "{%0,%1,%2,%3}, {%4,%5,%6,%7}, {%8,%9}, {%0,%1,%2,%3};"
        : "+f"(c[0]), "+f"(c[1]), "+f"(c[2]), "+f"(c[3])
        : "r"(a[0]), "r"(a[1]), "r"(a[2]), "r"(a[3]), "r"(b[0]), "r"(b[1]));
}

// ===========================================================================
// mma.sync split-bf16 GEMM.  CTA 128x256, K-chunk 32, **512 threads**
// (16 warps, warp tile 64x32 -> 4 warps/SMSP for latency hiding).
// 2-stage cp.async.  D += Ah*Bh + Ah*Bl + Al*Bh.
// ===========================================================================
#define ROWB    80
#define AARRB   (128 * ROWB)            // 10240
#define BARRB   (256 * ROWB)            // 20480
#define STAGEB  (2 * AARRB + 2 * BARRB) // 61440: [Ah][Al][Bh][Bl]
#define OFF_AL  (AARRB)
#define OFF_BH  (2 * AARRB)
#define OFF_BL  (2 * AARRB + BARRB)
#define GEMM_SMEM (2 * STAGEB)          // 122880

template <int EPI>
__global__ __launch_bounds__(512, 1)
void mma_gemm_kernel(const __nv_bfloat16* __restrict__ Ah_g,
                     const __nv_bfloat16* __restrict__ Al_g,
                     const __nv_bfloat16* __restrict__ Bh_g,
                     const __nv_bfloat16* __restrict__ Bl_g,
                     float* __restrict__ C, int M, int N, int K)
{
    extern __shared__ char smc[];
    const uint32_t smem_u32 = (uint32_t)__cvta_generic_to_shared(smc);

    const int tid  = threadIdx.x;
    const int lane = tid & 31;
    const int wid  = tid >> 5;           // 0..15
    const int wm   = wid & 1;            // 64-row half
    const int wn   = wid >> 1;           // 0..7: 32-col slice
    const int g    = lane >> 2;
    const int t    = lane & 3;
    const int m0   = blockIdx.y * 128;
    const int n0   = blockIdx.x * 256;

    const int ld_row = tid >> 2;         // 0..127
    const int ld_seg = tid & 3;

    float acc[4][4][4];
    #pragma unroll
    for (int a = 0; a < 4; a++)
        #pragma unroll
        for (int b = 0; b < 4; b++)
            #pragma unroll
            for (int c = 0; c < 4; c++) acc[a][b][c] = 0.0f;

    #define LOAD_STAGE(kt, s) do {                                            \
        uint32_t sb = smem_u32 + (s) * STAGEB;                                \
        {                                                                     \
            uint32_t so = sb + ld_row * ROWB + ld_seg * 16;                   \
            size_t  ga = (size_t)(m0 + ld_row) * K + (kt) * 32 + ld_seg * 8;  \
            CP16(so,          Ah_g + ga);                                     \
            CP16(so + OFF_AL, Al_g + ga);                                     \
        }                                                                     \
        _Pragma("unroll")                                                     \
        for (int i = 0; i < 2; i++) {                                         \
            int row = ld_row + i * 128;                                       \
            uint32_t so = sb + row * ROWB + ld_seg * 16;                      \
            size_t  gb = (size_t)(n0 + row) * K + (kt) * 32 + ld_seg * 8;     \
            CP16(so + OFF_BH, Bh_g + gb);                                     \
            CP16(so + OFF_BL, Bl_g + gb);                                     \
        }                                                                     \
    } while (0)

    const int nk = K >> 5;
    LOAD_STAGE(0, 0);
    CP_COMMIT();

    for (int kt = 0; kt < nk; kt++) {
        const int s = kt & 1;
        if (kt + 1 < nk) {
            LOAD_STAGE(kt + 1, s ^ 1);
            CP_COMMIT();
            CP_WAIT1();
        } else {
            CP_WAIT0();
        }
        __syncthreads();

        const char* st  = smc + s * STAGEB;
        const char* pAh = st;
        const char* pAl = st + OFF_AL;
        const char* pBh = st + OFF_BH;
        const char* pBl = st + OFF_BL;

        #pragma unroll
        for (int ks = 0; ks < 2; ks++) {
            const int kb = ks * 32;
            uint32_t af_h[4][4], af_l[4][4], bf_h[4][2], bf_l[4][2];
            #pragma unroll
            for (int mt = 0; mt < 4; mt++) {
                int off = (wm * 64 + mt * 16 + g) * ROWB + kb + t * 4;
                af_h[mt][0] = *(const uint32_t*)(pAh + off);
                af_h[mt][1] = *(const uint32_t*)(pAh + off + 8 * ROWB);
                af_h[mt][2] = *(const uint32_t*)(pAh + off + 16);
                af_h[mt][3] = *(const uint32_t*)(pAh + off + 8 * ROWB + 16);
                af_l[mt][0] = *(const uint32_t*)(pAl + off);
                af_l[mt][1] = *(const uint32_t*)(pAl + off + 8 * ROWB);
                af_l[mt][2] = *(const uint32_t*)(pAl + off + 16);
                af_l[mt][3] = *(const uint32_t*)(pAl + off + 8 * ROWB + 16);
            }
            #pragma unroll
            for (int nt = 0; nt < 4; nt++) {
                int off = (wn * 32 + nt * 8 + g) * ROWB + kb + t * 4;
                bf_h[nt][0] = *(const uint32_t*)(pBh + off);
                bf_h[nt][1] = *(const uint32_t*)(pBh + off + 16);
                bf_l[nt][0] = *(const uint32_t*)(pBl + off);
                bf_l[nt][1] = *(const uint32_t*)(pBl + off + 16);
            }
            // term-major: 3 passes of 16 independent MMAs
            #pragma unroll
            for (int mt = 0; mt < 4; mt++)
                #pragma unroll
                for (int nt = 0; nt < 4; nt++)
                    mma16816(acc[mt][nt], af_h[mt], bf_h[nt]);
            #pragma unroll
            for (int mt = 0; mt < 4; mt++)
                #pragma unroll
                for (int nt = 0; nt < 4; nt++)
                    mma16816(acc[mt][nt], af_h[mt], bf_l[nt]);
            #pragma unroll
            for (int mt = 0; mt < 4; mt++)
                #pragma unroll
                for (int nt = 0; nt < 4; nt++)
                    mma16816(acc[mt][nt], af_l[mt], bf_h[nt]);
        }
        __syncthreads();
    }
    #undef LOAD_STAGE

    #pragma unroll
    for (int mt = 0; mt < 4; mt++) {
        const int mr0 = m0 + wm * 64 + mt * 16 + g;
        #pragma unroll
        for (int nt = 0; nt < 4; nt++) {
            const int col = n0 + wn * 32 + nt * 8 + 2 * t;
            const float* a = acc[mt][nt];
            if (EPI == 2) {
                *reinterpret_cast<float2*>(C + (size_t)mr0 * N + col) =
                    make_float2(a[0], a[1]);
                *reinterpret_cast<float2*>(C + (size_t)(mr0 + 8) * N + col) =
                    make_float2(a[2], a[3]);
            } else {
                const int section = col >> 10;
                const int within  = col & 1023;
                const int h       = within >> 6;
                const int d       = within & 63;      // even
                #pragma unroll
                for (int rr = 0; rr < 2; rr++) {
                    const int m  = mr0 + rr * 8;
                    const int bb = m >> 11;
                    const int tt = m & 2047;
                    float e = a[rr * 2 + 0], o = a[rr * 2 + 1];
                    if (section == 2) {
                        size_t vb = ((size_t)(bb * NHEAD + h) * HDIM + d) * SEQ + tt;
                        __nv_bfloat16 h0, l0, h1, l1;
                        split2(e, h0, l0);
                        split2(o, h1, l1);
                        g_Vth[vb]       = h0;
                        g_Vtl[vb]       = l0;
                        g_Vth[vb + SEQ] = h1;
                        g_Vtl[vb + SEQ] = l1;
                    } else {
                        int idx = tt * HDIM + d;
                        float c0 = g_cos[idx],     s0 = g_sin[idx];
                        float c1 = g_cos[idx + 1], s1 = g_sin[idx + 1];
                        float r0 = e * c0 - o * s0;
                        float r1 = o * c1 + e * s1;
                        size_t base = ((size_t)(bb * NHEAD + h) * SEQ + tt) * HDIM + d;
                        __nv_bfloat16 h0, l0, h1, l1;
                        if (section == 0) {
                            r0 *= 0.125f; r1 *= 0.125f;
                            split2(r0, h0, l0); split2(r1, h1, l1);
                            *reinterpret_cast<uint32_t*>(g_Qh + base) = pack2(h0, h1);
                            *reinterpret_cast<uint32_t*>(g_Ql + base) = pack2(l0, l1);
                        } else {
                            split2(r0, h0, l0); split2(r1, h1, l1);
                            *reinterpret_cast<uint32_t*>(g_Kh + base) = pack2(h0, h1);
                            *reinterpret_cast<uint32_t*>(g_Kl + base) = pack2(l0, l1);
                        }
                    }
                }
            }
        }
    }
}

// ===========================================================================
// Tensor-core flash attention (unchanged from best; 256 threads).
// S = QhKh + QhKl + QlKh; P split in regs; O += PhVh + PhVl + PlVh.
// ===========================================================================
#define KROW    144
#define VROW    272
#define KTILE_B (128 * KROW)
#define VTILE_B (64 * VROW)
#define ATT_STAGE (2 * KTILE_B + 2 * VTILE_B)   // 71680
#define ATT_SMEM  (2 * ATT_STAGE)               // 143360

__global__ __launch_bounds__(256, 1)
void attn_mma_kernel()
{
    extern __shared__ char smc[];
    const uint32_t smem_u32 = (uint32_t)__cvta_generic_to_shared(smc);

    const int tid  = threadIdx.x;
    const int lane = tid & 31;
    const int w    = tid >> 5;
    const int g    = lane >> 2;
    const int t    = lane & 3;
    const int qt   = blockIdx.x;
    const int hh   = blockIdx.y;
    const int bb   = blockIdx.z;

    const size_t head_base = (size_t)(bb * NHEAD + hh) * SEQ * HDIM;
    const size_t vt_base   = (size_t)(bb * NHEAD + hh) * HDIM * SEQ;

    uint32_t qh[4][4], ql[4][4];
    {
        const int r0 = qt * 128 + w * 16 + g;
        const char* pqh = (const char*)(g_Qh + head_base);
        const char* pql = (const char*)(g_Ql + head_base);
        #pragma unroll
        for (int ks = 0; ks < 4; ks++) {
            int o00 = r0 * 128 + ks * 32 + t * 4;
            int o10 = o00 + 8 * 128;
            qh[ks][0] = *(const uint32_t*)(pqh + o00);
            qh[ks][1] = *(const uint32_t*)(pqh + o10);
            qh[ks][2] = *(const uint32_t*)(pqh + o00 + 16);
            qh[ks][3] = *(const uint32_t*)(pqh + o10 + 16);
            ql[ks][0] = *(const uint32_t*)(pql + o00);
            ql[ks][1] = *(const uint32_t*)(pql + o10);
            ql[ks][2] = *(const uint32_t*)(pql + o00 + 16);
            ql[ks][3] = *(const uint32_t*)(pql + o10 + 16);
        }
    }

    float m_[2] = {-INFINITY, -INFINITY};
    float l_[2] = {0.0f, 0.0f};
    float o[8][4];
    #pragma unroll
    for (int nt = 0; nt < 8; nt++)
        #pragma unroll
        for (int c = 0; c < 4; c++) o[nt][c] = 0.0f;

    #define LOAD_KV(kt, s) do {                                               \
        uint32_t sb = smem_u32 + (s) * ATT_STAGE;                             \
        _Pragma("unroll")                                                     \
        for (int i = 0; i < 4; i++) {                                         \
            int c    = tid + i * 256;                                         \
            int krow = c >> 3, kcc = c & 7;                                   \
            size_t kg = head_base + (size_t)((kt) * 128 + krow) * 64 + kcc * 8; \
            uint32_t kd = sb + krow * KROW + kcc * 16;                        \
            CP16(kd,            g_Kh + kg);                                   \
            CP16(kd + KTILE_B,  g_Kl + kg);                                   \
            int vrow = c >> 4, vcc = c & 15;                                  \
            size_t vg = vt_base + (size_t)vrow * SEQ + (kt) * 128 + vcc * 8;  \
            uint32_t vd = sb + 2 * KTILE_B + vrow * VROW + vcc * 16;          \
            CP16(vd,            g_Vth + vg);                                  \
            CP16(vd + VTILE_B,  g_Vtl + vg);                                  \
        }                                                                     \
    } while (0)

    LOAD_KV(0, 0);
    CP_COMMIT();

    const int nkt = SEQ / 128;
    for (int kt = 0; kt < nkt; kt++) {
        const int s = kt & 1;
        if (kt + 1 < nkt) {
            LOAD_KV(kt + 1, s ^ 1);
            CP_COMMIT();
            CP_WAIT1();
        } else {
            CP_WAIT0();
        }
        __syncthreads();

        const char* st   = smc + s * ATT_STAGE;
        const char* pKh  = st;
        const char* pKl  = st + KTILE_B;
        const char* pVh  = st + 2 * KTILE_B;
        const char* pVl  = st + 2 * KTILE_B + VTILE_B;

        float sacc[16][4];
        #pragma unroll
        for (int nt = 0; nt < 16; nt++)
            #pragma unroll
            for (int c = 0; c < 4; c++) sacc[nt][c] = 0.0f;

        #pragma unroll
        for (int ks = 0; ks < 4; ks++) {
            #pragma unroll
            for (int grp = 0; grp < 2; grp++) {
                uint32_t bh8[8][2], bl8[8][2];
                #pragma unroll
                for (int j = 0; j < 8; j++) {
                    const int nt = grp * 8 + j;
                    const int rowb = (nt * 8 + g) * KROW + ks * 32 + t * 4;
                    bh8[j][0] = *(const uint32_t*)(pKh + rowb);
                    bh8[j][1] = *(const uint32_t*)(pKh + rowb + 16);
                    bl8[j][0] = *(const uint32_t*)(pKl + rowb);
                    bl8[j][1] = *(const uint32_t*)(pKl + rowb + 16);
                }
                #pragma unroll
                for (int j = 0; j < 8; j++)
                    mma16816(sacc[grp * 8 + j], qh[ks], bh8[j]);
                #pragma unroll
                for (int j = 0; j < 8; j++)
                    mma16816(sacc[grp * 8 + j], qh[ks], bl8[j]);
                #pragma unroll
                for (int j = 0; j < 8; j++)
                    mma16816(sacc[grp * 8 + j], ql[ks], bh8[j]);
            }
        }

        float alpha[2];
        #pragma unroll
        for (int rr = 0; rr < 2; rr++) {
            float mx = -INFINITY;
            #pragma unroll
            for (int nt = 0; nt < 16; nt++)
                mx = fmaxf(mx, fmaxf(sacc[nt][rr * 2], sacc[nt][rr * 2 + 1]));
            mx = fmaxf(mx, __shfl_xor_sync(0xffffffffu, mx, 1));
            mx = fmaxf(mx, __shfl_xor_sync(0xffffffffu, mx, 2));
            float mnew = fmaxf(m_[rr], mx);
            alpha[rr] = __expf(m_[rr] - mnew);
            float sum = 0.0f;
            #pragma unroll
            for (int nt = 0; nt < 16; nt++) {
                float p0 = __expf(sacc[nt][rr * 2]     - mnew);
                float p1 = __expf(sacc[nt][rr * 2 + 1] - mnew);
                sacc[nt][rr * 2]     = p0;
                sacc[nt][rr * 2 + 1] = p1;
                sum += p0 + p1;
            }
            sum += __shfl_xor_sync(0xffffffffu, sum, 1);
            sum += __shfl_xor_sync(0xffffffffu, sum, 2);
            l_[rr] = l_[rr] * alpha[rr] + sum;
            m_[rr] = mnew;
        }
        #pragma unroll
        for (int nt = 0; nt < 8; nt++) {
            o[nt][0] *= alpha[0]; o[nt][1] *= alpha[0];
            o[nt][2] *= alpha[1]; o[nt][3] *= alpha[1];
        }

        uint32_t aph[8][4], apl[8][4];
        #pragma unroll
        for (int j = 0; j < 8; j++) {
            #pragma unroll
            for (int half = 0; half < 2; half++) {
                const float* sv = sacc[2 * j + half];
                __nv_bfloat16 h0, l0, h1, l1;
                split2(sv[0], h0, l0); split2(sv[1], h1, l1);
                aph[j][half * 2 + 0] = pack2(h0, h1);
                apl[j][half * 2 + 0] = pack2(l0, l1);
                split2(sv[2], h0, l0); split2(sv[3], h1, l1);
                aph[j][half * 2 + 1] = pack2(h0, h1);
                apl[j][half * 2 + 1] = pack2(l0, l1);
            }
        }

        #pragma unroll
        for (int j = 0; j < 8; j++) {
            uint32_t vh8[8][2], vl8[8][2];
            #pragma unroll
            for (int nt = 0; nt < 8; nt++) {
                const int rowb = (nt * 8 + g) * VROW + j * 32 + t * 4;
                vh8[nt][0] = *(const uint32_t*)(pVh + rowb);
                vh8[nt][1] = *(const uint32_t*)(pVh + rowb + 16);
                vl8[nt][0] = *(const uint32_t*)(pVl + rowb);
                vl8[nt][1] = *(const uint32_t*)(pVl + rowb + 16);
            }
            #pragma unroll
            for (int nt = 0; nt < 8; nt++)
                mma16816(o[nt], aph[j], vh8[nt]);
            #pragma unroll
            for (int nt = 0; nt < 8; nt++)
                mma16816(o[nt], aph[j], vl8[nt]);
            #pragma unroll
            for (int nt = 0; nt < 8; nt++)
                mma16816(o[nt], apl[j], vh8[nt]);
        }
        __syncthreads();
    }

    const float inv0 = 1.0f / l_[0];
    const float inv1 = 1.0f / l_[1];
    #pragma unroll
    for (int rr = 0; rr < 2; rr++) {
        const int row = qt * 128 + w * 16 + g + rr * 8;
        const float inv = rr ? inv1 : inv0;
        size_t base = ((size_t)bb * SEQ + row) * DMODEL + hh * HDIM;
        #pragma unroll
        for (int nt = 0; nt < 8; nt++) {
            const int d = nt * 8 + 2 * t;
            float y0 = o[nt][rr * 2]     * inv;
            float y1 = o[nt][rr * 2 + 1] * inv;
            __nv_bfloat16 h0, l0, h1, l1;
            split2(y0, h0, l0); split2(y1, h1, l1);
            *reinterpret_cast<uint32_t*>(g_yh + base + d) = pack2(h0, h1);
            *reinterpret_cast<uint32_t*>(g_yl + base + d) = pack2(l0, l1);
        }
    }
}

// ---------------------------------------------------------------------------
extern "C" void kernel_launch(void* const* d_in, const int* in_sizes, int n_in,
                              void* d_out, int out_size)
{
    const float* x     = (const float*)d_in[0];
    const float* w_qkv = (const float*)d_in[1];
    const float* w_out = (const float*)d_in[2];
    float* out = (float*)d_out;

    static bool attr_done = false;
    if (!attr_done) {
        cudaFuncSetAttribute(mma_gemm_kernel<1>,
                             cudaFuncAttributeMaxDynamicSharedMemorySize, GEMM_SMEM);
        cudaFuncSetAttribute(mma_gemm_kernel<2>,
                             cudaFuncAttributeMaxDynamicSharedMemorySize, GEMM_SMEM);
        cudaFuncSetAttribute(attn_mma_kernel,
                             cudaFuncAttributeMaxDynamicSharedMemorySize, ATT_SMEM);
        attr_done = true;
    }

    __nv_bfloat16 *xh, *xl, *yh, *yl, *wqh, *wql, *woh, *wol;
    cudaGetSymbolAddress((void**)&xh,  g_xh);
    cudaGetSymbolAddress((void**)&xl,  g_xl);
    cudaGetSymbolAddress((void**)&yh,  g_yh);
    cudaGetSymbolAddress((void**)&yl,  g_yl);
    cudaGetSymbolAddress((void**)&wqh, g_wqh);
    cudaGetSymbolAddress((void**)&wql, g_wql);
    cudaGetSymbolAddress((void**)&woh, g_woh);
    cudaGetSymbolAddress((void**)&wol, g_wol);

    prep_kernel<<<PREP_BLKS, 256>>>(x, w_qkv, w_out);

    mma_gemm_kernel<1><<<dim3(N_QKV / 256, BT / 128), 512, GEMM_SMEM>>>(
        xh, xl, wqh, wql, nullptr, BT, N_QKV, DMODEL);

    attn_mma_kernel<<<dim3(SEQ / 128, NHEAD, BATCH), 256, ATT_SMEM>>>();

    mma_gemm_kernel<2><<<dim3(DMODEL / 256, BT / 128), 512, GEMM_SMEM>>>(
        yh, yl, woh, wol, out, BT, DMODEL, DMODEL);
}